// round 17
// baseline (speedup 1.0000x reference)
#include <cuda_runtime.h>
#include <cuda_bf16.h>
#include <cstdint>

typedef unsigned long long u64;

__device__ float2 g_v[4][4096];
__device__ unsigned g_flag = 0;   // sim-done counter (target 4)
__device__ int g_done2 = 0;

__device__ __forceinline__ u64 pack2(float x, float y) {
    u64 u; asm("mov.b64 %0, {%1,%2};" : "=l"(u) : "f"(x), "f"(y)); return u;
}
__device__ __forceinline__ float2 unpack2(u64 u) {
    float2 v; asm("mov.b64 {%0,%1}, %2;" : "=f"(v.x), "=f"(v.y) : "l"(u)); return v;
}
__device__ __forceinline__ u64 swap2(u64 u) {
    float2 v = unpack2(u); return pack2(v.y, v.x);
}
__device__ __forceinline__ u64 fma2(u64 a, u64 b, u64 c) {
    u64 d; asm("fma.rn.f32x2 %0, %1, %2, %3;" : "=l"(d) : "l"(a), "l"(b), "l"(c)); return d;
}
__device__ __forceinline__ u64 mul2(u64 a, u64 b) {
    u64 d; asm("mul.rn.f32x2 %0, %1, %2;" : "=l"(d) : "l"(a), "l"(b)); return d;
}
__device__ __forceinline__ void red_release_add(unsigned* p, unsigned v) {
    asm volatile("red.release.gpu.global.add.u32 [%0], %1;" :: "l"(p), "r"(v) : "memory");
}
__device__ __forceinline__ unsigned ld_acquire(const unsigned* p) {
    unsigned v;
    asm volatile("ld.acquire.gpu.global.u32 %0, [%1];" : "=r"(v) : "l"(p) : "memory");
    return v;
}
__device__ __forceinline__ float2 cmulf(float2 a, float2 b) {
    return make_float2(a.x * b.x - a.y * b.y, a.x * b.y + a.y * b.x);
}
__device__ __forceinline__ float2 facsel(float2 e, int bit) {
    return bit ? e : make_float2(e.x, -e.y);
}

// Real-RY coef block per gate: [0]=cs=(c,c), [1]=coA=(-s,-s), [2]=coB=(s,s), [3]=coP=(-s,s)
struct SimSmem {
    u64 coef[96 * 4];
    float2 rawu[48];
    float2 ry0[8];
    float2 eph[96];
    float2 eom[96];
    float2 tabA[8][128];            // diag factors, Y bits 0..6
    float2 tabB[8][64];             // diag factors, Y bits 6..11
    u64 tX[2048]; u64 tY[2048];     // transpose staging
    u64 sX[2048]; u64 sY[2048];     // gather staging
};

// ---------------------------------------------------------------------------
// ONE CTA per column, 512 threads, 8 amps/thread. Amp Y: Y0=lam, Y1,Y2=p,
// Y3..7=lane t0..4, Y8..11=warp t5..8. Wire w acts on bit 11-w.
// Layer: RY gates on bits 0..7; transpose swaps {0,1,2}<->{8,9,10}; RY on
// wires 3,2,1 (now lam/p); local gather fuses wire-0 RY (branch m11=t8),
// CNOT perm m=Y^(Y>>1), and diag F_l(Y)=Omega_l(sigma Y)*Phi_{l+1}(Y).
// Staging float maps (both bit5 = t4; swizzle f^=(f>>5)&1 = store lane-swap):
//  T(Y)=Y0|Y3..7<<1|Y8..11<<6|Y1<<10|Y2<<11 ; H(m)=m8|m3..7<<1|m0..2<<6|m11<<9|m9<<10|m10<<11
// ---------------------------------------------------------------------------
template<int M>
__device__ __forceinline__ void gate_pairM(u64 AX[4], u64 AY[4], const u64* cc) {
    u64 cs = cc[0], coA = cc[1], coB = cc[2];
    #pragma unroll
    for (int p = 0; p < 4; p++) {
        if (p & M) continue;
        int q = p | M;
        u64 x0 = AX[p], y0 = AY[p], x1 = AX[q], y1 = AY[q];
        AX[p] = fma2(coA, x1, mul2(cs, x0));
        AY[p] = fma2(coA, y1, mul2(cs, y0));
        AX[q] = fma2(coB, x0, mul2(cs, x1));
        AY[q] = fma2(coB, y0, mul2(cs, y1));
    }
}
__device__ __forceinline__ void gate_pck(u64 AX[4], u64 AY[4], const u64* cc) {
    u64 cs = cc[0], coP = cc[3];
    #pragma unroll
    for (int p = 0; p < 4; p++) {
        u64 px = swap2(AX[p]), py = swap2(AY[p]);
        AX[p] = fma2(coP, px, mul2(cs, AX[p]));
        AY[p] = fma2(coP, py, mul2(cs, AY[p]));
    }
}
template<int LM, int K>
__device__ __forceinline__ void gate_lane(u64 AX[4], u64 AY[4], const u64* cc, int t) {
    u64 cs = cc[0];
    u64 co = ((t >> K) & 1) ? cc[2] : cc[1];
    #pragma unroll
    for (int p = 0; p < 4; p++) {
        u64 px = __shfl_xor_sync(0xffffffffu, AX[p], LM);
        u64 py = __shfl_xor_sync(0xffffffffu, AY[p], LM);
        AX[p] = fma2(co, px, mul2(cs, AX[p]));
        AY[p] = fma2(co, py, mul2(cs, AY[p]));
    }
}

__global__ __launch_bounds__(512, 1) void fused_kernel(
    const float* __restrict__ weights, const float* __restrict__ head_w,
    const float* __restrict__ head_b, const float* __restrict__ sb,
    float* __restrict__ out, int B, int nOut)
{
    extern __shared__ char smem_raw[];
    const int t = threadIdx.x;
    const int bid = blockIdx.x;

    if (bid < 4) {
        SimSmem* sm = (SimSmem*)smem_raw;
        const int col = bid, b0 = (col >> 1) & 1, b1 = col & 1;

        if (t < 96) {
            int l = t / 12, w = t % 12;
            float phi = weights[t * 3 + 0], th = weights[t * 3 + 1], om = weights[t * 3 + 2];
            float st, ct; sincosf(th * 0.5f, &st, &ct);
            float sphi, cphi; sincosf(phi * 0.5f, &sphi, &cphi);
            float som, com; sincosf(om * 0.5f, &som, &com);
            u64* c = sm->coef + t * 4;
            c[0] = pack2(ct, ct); c[1] = pack2(-st, -st);
            c[2] = pack2(st, st); c[3] = pack2(-st, st);
            sm->eph[t] = make_float2(cphi, sphi);
            sm->eom[t] = make_float2(com, som);
            if (w == 0) sm->ry0[l] = make_float2(ct, st);
            if (l == 0) {
                float cp = cphi * com - sphi * som, sp = sphi * com + cphi * som;
                float cd = cphi * com + sphi * som, sd = sphi * com - cphi * som;
                sm->rawu[w * 4 + 0] = make_float2( cp * ct, -sp * ct);
                sm->rawu[w * 4 + 1] = make_float2(-cd * st, -sd * st);
                sm->rawu[w * 4 + 2] = make_float2( cd * st, -sd * st);
                sm->rawu[w * 4 + 3] = make_float2( cp * ct,  sp * ct);
            }
        }
        __syncthreads();

        // diag tables (identical math to R15)
        for (int e = t; e < 1536; e += 512) {
            int l = e / 192, i = e - l * 192;
            float2 v = make_float2(1.f, 0.f);
            if (i < 128) {
                #pragma unroll
                for (int j = 0; j < 6; j++) {
                    int w = 11 - j;
                    if (l > 0) v = cmulf(v, facsel(sm->eom[l * 12 + w], ((i >> j) ^ (i >> (j + 1))) & 1));
                    if (l < 7) v = cmulf(v, facsel(sm->eph[(l + 1) * 12 + w], (i >> j) & 1));
                }
                sm->tabA[l][i] = v;
            } else {
                int b = i - 128;
                if (l > 0) {
                    #pragma unroll
                    for (int j = 6; j < 11; j++)
                        v = cmulf(v, facsel(sm->eom[l * 12 + 11 - j], ((b >> (j - 6)) ^ (b >> (j - 5))) & 1));
                    v = cmulf(v, facsel(sm->eom[l * 12 + 0], (b >> 5) & 1));
                }
                if (l < 7) {
                    #pragma unroll
                    for (int j = 6; j < 12; j++)
                        v = cmulf(v, facsel(sm->eph[(l + 1) * 12 + 11 - j], (b >> (j - 6)) & 1));
                }
                sm->tabB[l][b] = v;
            }
        }
        __syncthreads();

        // layer-invariant addresses
        const bool stSwap = (t >> 4) & 1;
        int baseT = ((t >> 5) & 1) | ((t & 31) << 1) | (((t >> 8) & 1) << 9)
                  | (((t >> 6) & 1) << 10) | (((t >> 7) & 1) << 11);
        baseT ^= (baseT >> 5) & 1;
        int h0 = (((t >> 5) ^ (t >> 6)) & 1)
               | ((((t) ^ (t >> 1)) & 1) << 1) | ((((t >> 1) ^ (t >> 2)) & 1) << 2)
               | ((((t >> 2) ^ (t >> 3)) & 1) << 3) | ((((t >> 3) ^ (t >> 4)) & 1) << 4)
               | ((((t >> 4) ^ (t >> 5)) & 1) << 5) | ((t & 1) << 8)
               | (((t >> 8) & 1) << 9) | ((((t >> 6) ^ (t >> 7)) & 1) << 10)
               | ((((t >> 7) ^ (t >> 8)) & 1) << 11);
        h0 ^= (h0 >> 5) & 1;
        const int iA = (t & 15) << 3;         // | p<<1 | lam
        const int bidx = (t >> 3) & 63;
        constexpr int dpv[4] = {0, 192, 384, 320};

        float* fTX = (float*)sm->tX; float* fTY = (float*)sm->tY;
        float* fSX = (float*)sm->sX; float* fSY = (float*)sm->sY;

        // analytic layer 0 (product state at m = Y^(Y>>1), incl wire0 + Phi_1)
        u64 AX[4], AY[4];
        {
            const float2* RU = sm->rawu;
            float2 P = RU[((t >> 8) & 1) * 2 + b0];
            P = cmulf(P, RU[4  + (((t >> 7) ^ (t >> 8)) & 1) * 2 + b1]);
            P = cmulf(P, RU[8  + (((t >> 6) ^ (t >> 7)) & 1) * 2]);
            P = cmulf(P, RU[12 + (((t >> 5) ^ (t >> 6)) & 1) * 2]);
            P = cmulf(P, RU[16 + (((t >> 4) ^ (t >> 5)) & 1) * 2]);
            P = cmulf(P, RU[20 + (((t >> 3) ^ (t >> 4)) & 1) * 2]);
            P = cmulf(P, RU[24 + (((t >> 2) ^ (t >> 3)) & 1) * 2]);
            P = cmulf(P, RU[28 + (((t >> 1) ^ (t >> 2)) & 1) * 2]);
            P = cmulf(P, RU[32 + ((t ^ (t >> 1)) & 1) * 2]);
            P = cmulf(P, sm->tabB[0][bidx]);
            #pragma unroll
            for (int p = 0; p < 4; p++) {
                int p0 = p & 1, p1 = (p >> 1) & 1;
                float2 Q = cmulf(P, RU[36 + ((p1 ^ t) & 1) * 2]);      // u9[m2=p1^t0]
                Q = cmulf(Q, RU[40 + (p0 ^ p1) * 2]);                  // u10[m1]
                float2 a0 = cmulf(cmulf(Q, RU[44 + p0 * 2]), sm->tabA[0][iA | (p << 1)]);
                float2 a1 = cmulf(cmulf(Q, RU[44 + (1 ^ p0) * 2]), sm->tabA[0][iA | (p << 1) | 1]);
                AX[p] = pack2(a0.x, a1.x);
                AY[p] = pack2(a0.y, a1.y);
            }
        }

        #pragma unroll 1
        for (int l = 1; l < 8; l++) {
            const u64* CG = sm->coef + l * 12 * 4;
            gate_pck    (AX, AY, CG + 11 * 4);          // bit0
            gate_pairM<1>(AX, AY, CG + 10 * 4);         // bit1
            gate_pairM<2>(AX, AY, CG + 9 * 4);          // bit2
            gate_lane<1, 0>(AX, AY, CG + 8 * 4, t);     // bit3
            gate_lane<2, 1>(AX, AY, CG + 7 * 4, t);     // bit4
            gate_lane<4, 2>(AX, AY, CG + 6 * 4, t);     // bit5
            gate_lane<8, 3>(AX, AY, CG + 5 * 4, t);     // bit6
            gate_lane<16, 4>(AX, AY, CG + 4 * 4, t);    // bit7
            // transpose {0,1,2} <-> {8,9,10}
            #pragma unroll
            for (int p = 0; p < 4; p++) {
                sm->tX[t | (p << 9)] = stSwap ? swap2(AX[p]) : AX[p];
                sm->tY[t | (p << 9)] = stSwap ? swap2(AY[p]) : AY[p];
            }
            __syncthreads();
            #pragma unroll
            for (int p = 0; p < 4; p++) {
                int a = baseT ^ (p << 7);
                AX[p] = pack2(fTX[a], fTX[a ^ 64]);
                AY[p] = pack2(fTY[a], fTY[a ^ 64]);
            }
            gate_pck    (AX, AY, CG + 3 * 4);
            gate_pairM<1>(AX, AY, CG + 2 * 4);
            gate_pairM<2>(AX, AY, CG + 1 * 4);
            // stage + local gather: wire-0 x diag F_l + CNOT perm
            #pragma unroll
            for (int p = 0; p < 4; p++) {
                sm->sX[t | (p << 9)] = stSwap ? swap2(AX[p]) : AX[p];
                sm->sY[t | (p << 9)] = stSwap ? swap2(AY[p]) : AY[p];
            }
            __syncthreads();
            {
                float2 Bf = sm->tabB[l][bidx];
                float2 r0 = sm->ry0[l];
                float c0 = r0.x;
                float co = ((t >> 8) & 1) ? r0.y : -r0.y;
                #pragma unroll
                for (int p = 0; p < 4; p++) {
                    float2 d0 = cmulf(sm->tabA[l][iA | (p << 1)], Bf);
                    float2 d1 = cmulf(sm->tabA[l][iA | (p << 1) | 1], Bf);
                    u64 sx  = pack2(c0 * d0.x, c0 * d1.x);
                    u64 sy  = pack2(c0 * d0.y, c0 * d1.y);
                    u64 nsy = pack2(-c0 * d0.y, -c0 * d1.y);
                    u64 ox  = pack2(co * d0.x, co * d1.x);
                    u64 oy  = pack2(co * d0.y, co * d1.y);
                    u64 noy = pack2(-co * d0.y, -co * d1.y);
                    int a0 = h0 ^ dpv[p];
                    int a1 = a0 ^ 64;
                    u64 VX = pack2(fSX[a0], fSX[a1]);
                    u64 VY = pack2(fSY[a0], fSY[a1]);
                    u64 PX = pack2(fSX[a0 ^ 512], fSX[a1 ^ 512]);
                    u64 PY = pack2(fSY[a0 ^ 512], fSY[a1 ^ 512]);
                    u64 nx = fma2(nsy, VY, mul2(sx, VX));
                    u64 ny = fma2(sy, VX, mul2(sx, VY));
                    AX[p] = fma2(noy, PY, fma2(ox, PX, nx));
                    AY[p] = fma2(oy, PX, fma2(ox, PY, ny));
                }
            }
            __syncthreads();   // staging buffers reused next iteration
        }

        // write column (natural order): Y = lam | p<<1 | (t&31)<<3 | (t>>5)<<8
        #pragma unroll
        for (int p = 0; p < 4; p++) {
            float2 xs = unpack2(AX[p]), ys = unpack2(AY[p]);
            int n0 = (p << 1) | ((t & 31) << 3) | (((t >> 5) & 15) << 8);
            g_v[col][n0]     = make_float2(xs.x, ys.x);
            g_v[col][n0 | 1] = make_float2(xs.y, ys.y);
        }
        __syncthreads();
        if (t == 0) red_release_add(&g_flag, 1u);
    } else {
        // ================= OUTPUT BLOCK =================
        const int i = (bid - 4) * 512 + t;
        float s0 = 0.f, c0 = 1.f, s1 = 0.f, c1 = 1.f, hb = head_b[0];
        if (i < B) {
            float t0 = sb[i * 8 + 0], t1 = sb[i * 8 + 1];
            sincosf(t0 * 0.5f, &s0, &c0);
            sincosf(t1 * 0.5f, &s1, &c1);
        }
        float hw[12];
        #pragma unroll
        for (int w = 0; w < 12; w++) hw[w] = head_w[w];

        if (t == 0) { while (ld_acquire(&g_flag) < 4u) __nanosleep(32); }
        __syncthreads();

        float2 acc[4][4];
        #pragma unroll
        for (int a = 0; a < 4; a++)
            #pragma unroll
            for (int b = 0; b < 4; b++) acc[a][b] = make_float2(0.f, 0.f);

        for (int idx = t; idx < 4096; idx += 512) {
            float s = 0.f;
            #pragma unroll
            for (int w = 0; w < 12; w++)
                s += ((idx >> (11 - w)) & 1) ? -hw[w] : hw[w];
            float2 v[4];
            #pragma unroll
            for (int a = 0; a < 4; a++) v[a] = g_v[a][idx];
            #pragma unroll
            for (int a = 0; a < 4; a++)
                #pragma unroll
                for (int b = 0; b < 4; b++) {
                    float pr = v[a].x * v[b].x + v[a].y * v[b].y;
                    float pi = v[a].y * v[b].x - v[a].x * v[b].y;
                    acc[a][b].x += s * pr;
                    acc[a][b].y += s * pi;
                }
        }

        float* red = (float*)smem_raw;
        float* Gs  = red + 16 * 32;
        float* flat = reinterpret_cast<float*>(acc);
        const int lane = t & 31, warp = t >> 5;
        #pragma unroll
        for (int comp = 0; comp < 32; comp++) {
            float v = flat[comp];
            #pragma unroll
            for (int off = 16; off; off >>= 1)
                v += __shfl_down_sync(0xffffffff, v, off);
            if (lane == 0) red[warp * 32 + comp] = v;
        }
        __syncthreads();
        if (t < 32) {
            float v = 0.f;
            #pragma unroll
            for (int w = 0; w < 16; w++) v += red[w * 32 + t];
            Gs[t] = v;
        }
        __syncthreads();

        if (t == 0) {
            int d = atomicAdd(&g_done2, 1);
            if (d == nOut - 1) { atomicExch(&g_flag, 0u); atomicExch(&g_done2, 0); }
        }

        if (i < B) {
            float2 c[4];
            c[0] = make_float2(c0 * c1, 0.f);
            c[1] = make_float2(c0 * s1, 0.f);
            c[2] = make_float2(0.f, -s0 * c1);
            c[3] = make_float2(0.f, -s0 * s1);
            float res = hb;
            #pragma unroll
            for (int jj = 0; jj < 4; jj++)
                #pragma unroll
                for (int k = 0; k < 4; k++) {
                    float ccr = c[jj].x * c[k].x + c[jj].y * c[k].y;
                    float cci = c[jj].y * c[k].x - c[jj].x * c[k].y;
                    res += ccr * Gs[(jj * 4 + k) * 2] - cci * Gs[(jj * 4 + k) * 2 + 1];
                }
            out[i] = res;
        }
    }
}

extern "C" void kernel_launch(void* const* d_in, const int* in_sizes, int n_in,
                              void* d_out, int out_size) {
    const float* state_batch = (const float*)d_in[0];
    const float* weights     = (const float*)d_in[1];
    const float* head_w      = (const float*)d_in[2];
    const float* head_b      = (const float*)d_in[3];
    float* out = (float*)d_out;
    const int B = in_sizes[0] / 8;

    const int smem_bytes = (int)sizeof(SimSmem);
    cudaFuncSetAttribute(fused_kernel, cudaFuncAttributeMaxDynamicSharedMemorySize,
                         smem_bytes);
    const int nOut = (B + 511) / 512;
    fused_kernel<<<4 + nOut, 512, smem_bytes>>>(weights, head_w, head_b,
                                                state_batch, out, B, nOut);
}